// round 5
// baseline (speedup 1.0000x reference)
#include <cuda_runtime.h>
#include <cuda_fp16.h>

#define NN      50000
#define FDIM    256
#define H1DIM   128
#define NHEADS  8
#define CDIM2   16
#define EMAX    1100000
#define NBLK    196              // ceil(50000/256)

// ---- scratch (__device__ globals; no allocation allowed) -------------------
__device__ __half g_hp1h[NN * H1DIM];  // layer1 GEMM output, fp16 (gathered a lot)
__device__ float g_as1[NN * NHEADS];
__device__ float g_ad1[NN * NHEADS];
__device__ float g_h1[NN * H1DIM];
__device__ float g_h2[NN * CDIM2];
__device__ float g_as2[NN];
__device__ float g_ad2[NN];
__device__ int g_deg[NN];              // zero-initialized; re-zeroed by agg2 tail
__device__ int g_off[NN + 1];
__device__ int g_cur[NN];
__device__ int g_bsum[NBLK];
__device__ int g_eidx[EMAX];

// ---------------------------------------------------------------------------
// CSR build
// ---------------------------------------------------------------------------
// 4 edges per thread (coalesced; batched independent atomics for ILP)
__global__ void hist_kernel(const int* __restrict__ ei, int E) {
    int i0 = (blockIdx.x * blockDim.x + threadIdx.x) * 4;
    if (i0 >= E) return;
    int n = min(4, E - i0);
    int d0, d1, d2, d3;
    d0 = ei[E + i0];
    if (n > 1) d1 = ei[E + i0 + 1];
    if (n > 2) d2 = ei[E + i0 + 2];
    if (n > 3) d3 = ei[E + i0 + 3];
    atomicAdd(&g_deg[d0], 1);
    if (n > 1) atomicAdd(&g_deg[d1], 1);
    if (n > 2) atomicAdd(&g_deg[d2], 1);
    if (n > 3) atomicAdd(&g_deg[d3], 1);
}

// per-block reduction of (deg+1)
__global__ void scanA_kernel() {
    __shared__ int buf[256];
    int i = blockIdx.x * 256 + threadIdx.x;
    int v = (i < NN) ? g_deg[i] + 1 : 0;   // +1 = self-loop
    buf[threadIdx.x] = v;
    __syncthreads();
#pragma unroll
    for (int off = 128; off >= 1; off >>= 1) {
        if (threadIdx.x < off) buf[threadIdx.x] += buf[threadIdx.x + off];
        __syncthreads();
    }
    if (threadIdx.x == 0) g_bsum[blockIdx.x] = buf[0];
}

// per-block scan + (redundant) scan of block sums -> g_off / g_cur
__global__ void scanC_kernel() {
    __shared__ int bbuf[256];
    __shared__ int wsum[8];
    int t = threadIdx.x, lane = t & 31, wid = t >> 5;
    // inline scan of the 196 block sums (every block does it; cheap)
    int bv = (t < NBLK) ? g_bsum[t] : 0;
    bbuf[t] = bv;
    __syncthreads();
#pragma unroll
    for (int off = 1; off < 256; off <<= 1) {
        int n = (t >= off) ? bbuf[t - off] : 0;
        __syncthreads();
        bbuf[t] += n;
        __syncthreads();
    }
    int boff = (blockIdx.x > 0) ? bbuf[blockIdx.x - 1] : 0;
    if (blockIdx.x == 0 && t == 0) g_off[NN] = bbuf[NBLK - 1];
    // per-node scan within this block
    int i = blockIdx.x * 256 + t;
    int v = (i < NN) ? g_deg[i] + 1 : 0;
    int incl = v;
#pragma unroll
    for (int off = 1; off < 32; off <<= 1) {
        int n = __shfl_up_sync(0xffffffffu, incl, off);
        if (lane >= off) incl += n;
    }
    if (lane == 31) wsum[wid] = incl;
    __syncthreads();
    if (wid == 0 && lane < 8) {
        int s = wsum[lane];
#pragma unroll
        for (int off = 1; off < 8; off <<= 1) {
            int n = __shfl_up_sync(0x000000ffu, s, off);
            if (lane >= off) s += n;
        }
        wsum[lane] = s;
    }
    __syncthreads();
    int woff = (wid > 0) ? wsum[wid - 1] : 0;
    int excl = boff + woff + incl - v;
    if (i < NN) { g_off[i] = excl; g_cur[i] = excl; }
}

// 2 real edges per thread + self-loop range (+ odd-E tail)
__global__ void scatter_kernel(const int* __restrict__ ei, int E) {
    int pairs = E >> 1;
    int idx = blockIdx.x * blockDim.x + threadIdx.x;
    if (idx < pairs) {
        int e = idx * 2;
        int s0 = ei[e], s1 = ei[e + 1];
        int d0 = ei[E + e], d1 = ei[E + e + 1];
        int p0 = atomicAdd(&g_cur[d0], 1);
        int p1 = atomicAdd(&g_cur[d1], 1);
        g_eidx[p0] = s0;
        g_eidx[p1] = s1;
    } else if (idx < pairs + NN) {
        int n = idx - pairs;
        int p = atomicAdd(&g_cur[n], 1);
        g_eidx[p] = n;
    } else if ((E & 1) && idx == pairs + NN) {
        int s = ei[E - 1], d = ei[E + E - 1];
        int p = atomicAdd(&g_cur[d], 1);
        g_eidx[p] = s;
    }
}

// ---------------------------------------------------------------------------
// GEMM1 (fp16 MMA, fp32 accum): g_hp1h[N,128] = half(x[N,256] @ W1[256,128])
// 128x128 tile, 8 warps in 4(m)x2(n); each warp 32x64 via m16n8k16.
// ---------------------------------------------------------------------------
__global__ void __launch_bounds__(256) gemm1_kernel(const float* __restrict__ X,
                                                    const float* __restrict__ W) {
    __shared__ __align__(16) __half As[128][40];   // [m][k], 32 data + 8 pad
    __shared__ __align__(16) __half Bt[128][40];   // [n][k]
    const int tid = threadIdx.x;
    const int warp = tid >> 5, lane = tid & 31;
    const int wm = warp >> 1, wn = warp & 1;
    const int row0 = blockIdx.x * 128;
    const int gid = lane >> 2, qid = lane & 3;

    float acc[2][8][4];
#pragma unroll
    for (int mt = 0; mt < 2; mt++)
#pragma unroll
        for (int nt = 0; nt < 8; nt++)
#pragma unroll
            for (int j = 0; j < 4; j++) acc[mt][nt][j] = 0.f;

    for (int k0 = 0; k0 < FDIM; k0 += 32) {
        // A tile: 128x32 -> fp16
#pragma unroll
        for (int t = 0; t < 4; t++) {
            int i = tid + t * 256;
            int r = i >> 3, c = (i & 7) << 2;
            float4 v = make_float4(0.f, 0.f, 0.f, 0.f);
            if (row0 + r < NN) v = *(const float4*)(X + (size_t)(row0 + r) * FDIM + k0 + c);
            *(__half2*)&As[r][c]     = __floats2half2_rn(v.x, v.y);
            *(__half2*)&As[r][c + 2] = __floats2half2_rn(v.z, v.w);
        }
        // B tile: 32(k)x128(n), stored transposed [n][k] as fp16
#pragma unroll
        for (int t = 0; t < 4; t++) {
            int i = tid + t * 256;
            int r = i & 31;             // k within chunk
            int c = (i >> 5) << 2;      // n
            float4 v = *(const float4*)(W + (size_t)(k0 + r) * H1DIM + c);
            Bt[c + 0][r] = __float2half_rn(v.x);
            Bt[c + 1][r] = __float2half_rn(v.y);
            Bt[c + 2][r] = __float2half_rn(v.z);
            Bt[c + 3][r] = __float2half_rn(v.w);
        }
        __syncthreads();
#pragma unroll
        for (int kk = 0; kk < 2; kk++) {
            const int ks = kk * 16;
            unsigned a[2][4], b[8][2];
#pragma unroll
            for (int mt = 0; mt < 2; mt++) {
                int rw = wm * 32 + mt * 16 + gid;
                a[mt][0] = *(const unsigned*)&As[rw][ks + qid * 2];
                a[mt][1] = *(const unsigned*)&As[rw + 8][ks + qid * 2];
                a[mt][2] = *(const unsigned*)&As[rw][ks + 8 + qid * 2];
                a[mt][3] = *(const unsigned*)&As[rw + 8][ks + 8 + qid * 2];
            }
#pragma unroll
            for (int nt = 0; nt < 8; nt++) {
                int cl = wn * 64 + nt * 8 + gid;
                b[nt][0] = *(const unsigned*)&Bt[cl][ks + qid * 2];
                b[nt][1] = *(const unsigned*)&Bt[cl][ks + 8 + qid * 2];
            }
#pragma unroll
            for (int mt = 0; mt < 2; mt++)
#pragma unroll
                for (int nt = 0; nt < 8; nt++) {
                    asm volatile(
                        "mma.sync.aligned.m16n8k16.row.col.f32.f16.f16.f32 "
                        "{%0,%1,%2,%3}, {%4,%5,%6,%7}, {%8,%9}, {%0,%1,%2,%3};\n"
                        : "+f"(acc[mt][nt][0]), "+f"(acc[mt][nt][1]),
                          "+f"(acc[mt][nt][2]), "+f"(acc[mt][nt][3])
                        : "r"(a[mt][0]), "r"(a[mt][1]), "r"(a[mt][2]), "r"(a[mt][3]),
                          "r"(b[nt][0]), "r"(b[nt][1]));
                }
        }
        __syncthreads();
    }
    // epilogue: c0/c1 adjacent cols at row rw; c2/c3 at rw+8. Store as half2.
#pragma unroll
    for (int mt = 0; mt < 2; mt++) {
        int rw = row0 + wm * 32 + mt * 16 + gid;
#pragma unroll
        for (int nt = 0; nt < 8; nt++) {
            int cl = wn * 64 + nt * 8 + qid * 2;
            if (rw < NN)
                *(__half2*)(g_hp1h + (size_t)rw * H1DIM + cl) =
                    __floats2half2_rn(acc[mt][nt][0], acc[mt][nt][1]);
            if (rw + 8 < NN)
                *(__half2*)(g_hp1h + (size_t)(rw + 8) * H1DIM + cl) =
                    __floats2half2_rn(acc[mt][nt][2], acc[mt][nt][3]);
        }
    }
}

// ---------------------------------------------------------------------------
// alpha1: per-node attention logits from fp16 h. One warp per node.
// ---------------------------------------------------------------------------
__global__ void alpha1_kernel(const float* __restrict__ att_src, const float* __restrict__ att_dst) {
    int gw = (blockIdx.x * blockDim.x + threadIdx.x) >> 5;
    int lane = threadIdx.x & 31;
    if (gw >= NN) return;
    int head = lane >> 2, sub = lane & 3;
    const __half2* hp = (const __half2*)(g_hp1h + (size_t)gw * H1DIM + lane * 4);
    float2 h01 = __half22float2(hp[0]);
    float2 h23 = __half22float2(hp[1]);
    const float* As = att_src + head * 16 + sub * 4;
    const float* Ad = att_dst + head * 16 + sub * 4;
    float s = h01.x * As[0] + h01.y * As[1] + h23.x * As[2] + h23.y * As[3];
    float d = h01.x * Ad[0] + h01.y * Ad[1] + h23.x * Ad[2] + h23.y * Ad[3];
    s += __shfl_xor_sync(0xffffffffu, s, 1);
    s += __shfl_xor_sync(0xffffffffu, s, 2);
    d += __shfl_xor_sync(0xffffffffu, d, 1);
    d += __shfl_xor_sync(0xffffffffu, d, 2);
    if (sub == 0) { g_as1[gw * 8 + head] = s; g_ad1[gw * 8 + head] = d; }
}

// ---------------------------------------------------------------------------
// agg1: CSR gather (fp16 h) + softmax-normalize + bias + ELU. Warp per node.
// ---------------------------------------------------------------------------
__device__ __forceinline__ float edge_w1(int s, int head, float myad) {
    float t = __ldg(g_as1 + s * 8 + head) + myad;
    t = t > 0.f ? t : 0.2f * t;
    return __expf(t);
}

__device__ __forceinline__ void gather_h(int s, int lane, float2& x01, float2& x23) {
    const __half2* hp = (const __half2*)(g_hp1h + (size_t)s * H1DIM + lane * 4);
    x01 = __half22float2(hp[0]);
    x23 = __half22float2(hp[1]);
}

__global__ void __launch_bounds__(256) agg1_kernel(const float* __restrict__ b1) {
    int gw = (blockIdx.x * blockDim.x + threadIdx.x) >> 5;
    int lane = threadIdx.x & 31;
    if (gw >= NN) return;
    int head = lane >> 2;
    int beg = g_off[gw], end = g_off[gw + 1];
    float myad = g_ad1[gw * 8 + head];
    float a0 = 0.f, a1 = 0.f, a2 = 0.f, a3 = 0.f, den = 0.f;
    int p = beg;
    for (; p + 4 <= end; p += 4) {
        int s0 = g_eidx[p], s1 = g_eidx[p + 1], s2 = g_eidx[p + 2], s3 = g_eidx[p + 3];
        float w0 = edge_w1(s0, head, myad);
        float w1 = edge_w1(s1, head, myad);
        float w2 = edge_w1(s2, head, myad);
        float w3 = edge_w1(s3, head, myad);
        float2 h0a, h0b, h1a, h1b, h2a, h2b, h3a, h3b;
        gather_h(s0, lane, h0a, h0b);
        gather_h(s1, lane, h1a, h1b);
        gather_h(s2, lane, h2a, h2b);
        gather_h(s3, lane, h3a, h3b);
        den += (w0 + w1) + (w2 + w3);
        a0 += w0 * h0a.x + w1 * h1a.x + w2 * h2a.x + w3 * h3a.x;
        a1 += w0 * h0a.y + w1 * h1a.y + w2 * h2a.y + w3 * h3a.y;
        a2 += w0 * h0b.x + w1 * h1b.x + w2 * h2b.x + w3 * h3b.x;
        a3 += w0 * h0b.y + w1 * h1b.y + w2 * h2b.y + w3 * h3b.y;
    }
    for (; p < end; p++) {
        int s = g_eidx[p];
        float w = edge_w1(s, head, myad);
        float2 ha, hb;
        gather_h(s, lane, ha, hb);
        den += w;
        a0 += w * ha.x; a1 += w * ha.y; a2 += w * hb.x; a3 += w * hb.y;
    }
    float inv = __frcp_rn(den);
    const float* bb = b1 + lane * 4;
    float v0 = a0 * inv + bb[0];
    float v1 = a1 * inv + bb[1];
    float v2 = a2 * inv + bb[2];
    float v3 = a3 * inv + bb[3];
    v0 = v0 > 0.f ? v0 : expm1f(v0);
    v1 = v1 > 0.f ? v1 : expm1f(v1);
    v2 = v2 > 0.f ? v2 : expm1f(v2);
    v3 = v3 > 0.f ? v3 : expm1f(v3);
    *(float4*)(g_h1 + (size_t)gw * H1DIM + lane * 4) = make_float4(v0, v1, v2, v3);
}

// ---------------------------------------------------------------------------
// GEMM2 + alpha2 fused
// ---------------------------------------------------------------------------
__global__ void __launch_bounds__(256) gemm2_kernel(const float* __restrict__ W2,
                             const float* __restrict__ as2w, const float* __restrict__ ad2w) {
    __shared__ __align__(16) float Ws[128 * 16];
    __shared__ __align__(16) float Hs[16][132];
    const int tid = threadIdx.x;
    const int row0 = blockIdx.x * 16;
#pragma unroll
    for (int t = 0; t < 2; t++) {
        int i = (tid + t * 256) * 4;
        *(float4*)&Ws[i] = *(const float4*)(W2 + i);
    }
#pragma unroll
    for (int t = 0; t < 2; t++) {
        int i = tid + t * 256;
        int r = i >> 5, c = (i & 31) << 2;
        float4 v = make_float4(0.f, 0.f, 0.f, 0.f);
        int gr = row0 + r;
        if (gr < NN) v = *(const float4*)(g_h1 + (size_t)gr * H1DIM + c);
        *(float4*)&Hs[r][c] = v;
    }
    __syncthreads();
    const int r = tid >> 4, c = tid & 15;
    float s = 0.f;
#pragma unroll
    for (int k = 0; k < 128; k++) s += Hs[r][k] * Ws[k * 16 + c];
    float sv = s * as2w[c], dv = s * ad2w[c];
#pragma unroll
    for (int off = 8; off >= 1; off >>= 1) {
        sv += __shfl_down_sync(0xffffffffu, sv, off, 16);
        dv += __shfl_down_sync(0xffffffffu, dv, off, 16);
    }
    int gr = row0 + r;
    if (gr < NN) {
        g_h2[gr * 16 + c] = s;
        if (c == 0) { g_as2[gr] = sv; g_ad2[gr] = dv; }
    }
}

// ---------------------------------------------------------------------------
// agg2: one warp per dst node; two 16-lane groups; unroll x2.
// Tail: re-zero g_deg for the next replay (keeps graph-replay invariant).
// ---------------------------------------------------------------------------
__global__ void __launch_bounds__(256) agg2_kernel(const float* __restrict__ b2,
                                                   float* __restrict__ out) {
    int gw = (blockIdx.x * blockDim.x + threadIdx.x) >> 5;
    int lane = threadIdx.x & 31;
    if (gw >= NN) return;
    int beg = g_off[gw], end = g_off[gw + 1];
    int grp = lane >> 4, fl = lane & 15;
    float ad = g_ad2[gw];
    float acc = 0.f, den = 0.f;
    int p = beg + grp;
    for (; p + 2 < end; p += 4) {
        int s0 = g_eidx[p], s1 = g_eidx[p + 2];
        float t0 = g_as2[s0] + ad, t1 = g_as2[s1] + ad;
        t0 = t0 > 0.f ? t0 : 0.2f * t0;
        t1 = t1 > 0.f ? t1 : 0.2f * t1;
        float w0 = __expf(t0), w1 = __expf(t1);
        float v0 = g_h2[s0 * 16 + fl], v1 = g_h2[s1 * 16 + fl];
        den += w0 + w1;
        acc += w0 * v0 + w1 * v1;
    }
    if (p < end) {
        int s = g_eidx[p];
        float t = g_as2[s] + ad;
        t = t > 0.f ? t : 0.2f * t;
        float w = __expf(t);
        den += w;
        acc += w * g_h2[s * 16 + fl];
    }
    acc += __shfl_xor_sync(0xffffffffu, acc, 16);
    den += __shfl_xor_sync(0xffffffffu, den, 16);
    if (grp == 0) out[gw * 16 + fl] = acc * __frcp_rn(den) + b2[fl];
    if (lane == 0) g_deg[gw] = 0;   // reset for next graph replay
}

// ---------------------------------------------------------------------------
extern "C" void kernel_launch(void* const* d_in, const int* in_sizes, int n_in,
                              void* d_out, int out_size) {
    const float* x   = (const float*)d_in[0];
    const int*   ei  = (const int*)d_in[1];
    const float* W1  = (const float*)d_in[2];
    const float* as1 = (const float*)d_in[3];
    const float* ad1 = (const float*)d_in[4];
    const float* b1  = (const float*)d_in[5];
    const float* W2  = (const float*)d_in[6];
    const float* as2 = (const float*)d_in[7];
    const float* ad2 = (const float*)d_in[8];
    const float* b2  = (const float*)d_in[9];
    const int E = in_sizes[1] / 2;
    const int scat_threads = (E >> 1) + NN + 1;

    hist_kernel<<<((E + 3) / 4 + 255) / 256, 256>>>(ei, E);
    scanA_kernel<<<NBLK, 256>>>();
    scanC_kernel<<<NBLK, 256>>>();
    scatter_kernel<<<(scat_threads + 255) / 256, 256>>>(ei, E);

    gemm1_kernel<<<(NN + 127) / 128, 256>>>(x, W1);
    alpha1_kernel<<<(NN * 32 + 255) / 256, 256>>>(as1, ad1);
    agg1_kernel<<<(NN * 32 + 255) / 256, 256>>>(b1);
    gemm2_kernel<<<(NN + 15) / 16, 256>>>(W2, as2, ad2);
    agg2_kernel<<<(NN * 32 + 255) / 256, 256>>>(b2, (float*)d_out);
}

// round 6
// speedup vs baseline: 1.0233x; 1.0233x over previous
#include <cuda_runtime.h>

#define NN      50000
#define FDIM    256
#define H1DIM   128
#define NHEADS  8
#define CDIM2   16
#define CAP     96               // max in-degree bucket capacity (Poisson(16) tail: safe)

// ---- scratch (__device__ globals; no allocation allowed) -------------------
__device__ float g_hp1[NN * H1DIM];
__device__ float g_as1[NN * NHEADS];
__device__ float g_ad1[NN * NHEADS];
__device__ float g_h1[NN * H1DIM];
__device__ float g_h2[NN * CDIM2];
__device__ float g_as2[NN];
__device__ float g_ad2[NN];
__device__ int g_deg[NN];              // zero-init; re-zeroed by agg2 tail each launch
__device__ int g_eidx[NN * CAP];       // bucketed incoming-edge src lists

__device__ __forceinline__ unsigned f2tf32(float x) {
    unsigned r; asm("cvt.rna.tf32.f32 %0, %1;" : "=r"(r) : "f"(x)); return r;
}

// ---------------------------------------------------------------------------
// scatter: single-pass bucket build. 4 real edges per thread + self-loop range.
// ---------------------------------------------------------------------------
__global__ void scatter_kernel(const int* __restrict__ ei, int E) {
    int quads = (E + 3) >> 2;
    int idx = blockIdx.x * blockDim.x + threadIdx.x;
    if (idx < quads) {
        int e0 = idx * 4;
        int n = min(4, E - e0);
        int s0, s1, s2, s3, d0, d1, d2, d3;
        s0 = ei[e0];     d0 = ei[E + e0];
        if (n > 1) { s1 = ei[e0 + 1]; d1 = ei[E + e0 + 1]; }
        if (n > 2) { s2 = ei[e0 + 2]; d2 = ei[E + e0 + 2]; }
        if (n > 3) { s3 = ei[e0 + 3]; d3 = ei[E + e0 + 3]; }
        int p0 = atomicAdd(&g_deg[d0], 1);
        int p1 = (n > 1) ? atomicAdd(&g_deg[d1], 1) : 0;
        int p2 = (n > 2) ? atomicAdd(&g_deg[d2], 1) : 0;
        int p3 = (n > 3) ? atomicAdd(&g_deg[d3], 1) : 0;
        g_eidx[d0 * CAP + p0] = s0;
        if (n > 1) g_eidx[d1 * CAP + p1] = s1;
        if (n > 2) g_eidx[d2 * CAP + p2] = s2;
        if (n > 3) g_eidx[d3 * CAP + p3] = s3;
    } else if (idx < quads + NN) {
        int nd = idx - quads;
        int p = atomicAdd(&g_deg[nd], 1);
        g_eidx[nd * CAP + p] = nd;     // self-loop
    }
}

// ---------------------------------------------------------------------------
// GEMM1 (tf32 MMA): g_hp1[N,128] = x[N,256] @ W1[256,128]
// ---------------------------------------------------------------------------
__global__ void __launch_bounds__(256) gemm1_kernel(const float* __restrict__ X,
                                                    const float* __restrict__ W) {
    __shared__ __align__(16) float As[128][36];
    __shared__ __align__(16) float Bt[128][36];
    const int tid = threadIdx.x;
    const int warp = tid >> 5, lane = tid & 31;
    const int wm = warp >> 1, wn = warp & 1;
    const int row0 = blockIdx.x * 128;
    const int gid = lane >> 2, qid = lane & 3;

    float acc[2][8][4];
#pragma unroll
    for (int mt = 0; mt < 2; mt++)
#pragma unroll
        for (int nt = 0; nt < 8; nt++)
#pragma unroll
            for (int j = 0; j < 4; j++) acc[mt][nt][j] = 0.f;

    for (int k0 = 0; k0 < FDIM; k0 += 32) {
#pragma unroll
        for (int t = 0; t < 4; t++) {
            int i = tid + t * 256;
            int r = i >> 3, c = (i & 7) << 2;
            float4 v = make_float4(0.f, 0.f, 0.f, 0.f);
            if (row0 + r < NN) v = *(const float4*)(X + (size_t)(row0 + r) * FDIM + k0 + c);
            float4 o;
            o.x = __uint_as_float(f2tf32(v.x));
            o.y = __uint_as_float(f2tf32(v.y));
            o.z = __uint_as_float(f2tf32(v.z));
            o.w = __uint_as_float(f2tf32(v.w));
            *(float4*)&As[r][c] = o;
        }
#pragma unroll
        for (int t = 0; t < 4; t++) {
            int i = tid + t * 256;
            int r = i & 31;
            int c = (i >> 5) << 2;
            float4 v = *(const float4*)(W + (size_t)(k0 + r) * H1DIM + c);
            Bt[c + 0][r] = __uint_as_float(f2tf32(v.x));
            Bt[c + 1][r] = __uint_as_float(f2tf32(v.y));
            Bt[c + 2][r] = __uint_as_float(f2tf32(v.z));
            Bt[c + 3][r] = __uint_as_float(f2tf32(v.w));
        }
        __syncthreads();
#pragma unroll
        for (int kk = 0; kk < 4; kk++) {
            const int k = kk * 8;
            unsigned a[2][4], b[8][2];
#pragma unroll
            for (int mt = 0; mt < 2; mt++) {
                int rw = wm * 32 + mt * 16 + gid;
                a[mt][0] = __float_as_uint(As[rw][k + qid]);
                a[mt][1] = __float_as_uint(As[rw + 8][k + qid]);
                a[mt][2] = __float_as_uint(As[rw][k + 4 + qid]);
                a[mt][3] = __float_as_uint(As[rw + 8][k + 4 + qid]);
            }
#pragma unroll
            for (int nt = 0; nt < 8; nt++) {
                int cl = wn * 64 + nt * 8 + gid;
                b[nt][0] = __float_as_uint(Bt[cl][k + qid]);
                b[nt][1] = __float_as_uint(Bt[cl][k + 4 + qid]);
            }
#pragma unroll
            for (int mt = 0; mt < 2; mt++)
#pragma unroll
                for (int nt = 0; nt < 8; nt++) {
                    asm volatile(
                        "mma.sync.aligned.m16n8k8.row.col.f32.tf32.tf32.f32 "
                        "{%0,%1,%2,%3}, {%4,%5,%6,%7}, {%8,%9}, {%0,%1,%2,%3};\n"
                        : "+f"(acc[mt][nt][0]), "+f"(acc[mt][nt][1]),
                          "+f"(acc[mt][nt][2]), "+f"(acc[mt][nt][3])
                        : "r"(a[mt][0]), "r"(a[mt][1]), "r"(a[mt][2]), "r"(a[mt][3]),
                          "r"(b[nt][0]), "r"(b[nt][1]));
                }
        }
        __syncthreads();
    }
#pragma unroll
    for (int mt = 0; mt < 2; mt++) {
        int rw = row0 + wm * 32 + mt * 16 + gid;
#pragma unroll
        for (int nt = 0; nt < 8; nt++) {
            int cl = wn * 64 + nt * 8 + qid * 2;
            if (rw < NN)
                *(float2*)(g_hp1 + (size_t)rw * H1DIM + cl) =
                    make_float2(acc[mt][nt][0], acc[mt][nt][1]);
            if (rw + 8 < NN)
                *(float2*)(g_hp1 + (size_t)(rw + 8) * H1DIM + cl) =
                    make_float2(acc[mt][nt][2], acc[mt][nt][3]);
        }
    }
}

// ---------------------------------------------------------------------------
// alpha1: per-node attention logits. One warp per node.
// ---------------------------------------------------------------------------
__global__ void alpha1_kernel(const float* __restrict__ att_src, const float* __restrict__ att_dst) {
    int gw = (blockIdx.x * blockDim.x + threadIdx.x) >> 5;
    int lane = threadIdx.x & 31;
    if (gw >= NN) return;
    int head = lane >> 2, sub = lane & 3;
    float4 h = *(const float4*)(g_hp1 + (size_t)gw * H1DIM + lane * 4);
    const float* As = att_src + head * 16 + sub * 4;
    const float* Ad = att_dst + head * 16 + sub * 4;
    float s = h.x * As[0] + h.y * As[1] + h.z * As[2] + h.w * As[3];
    float d = h.x * Ad[0] + h.y * Ad[1] + h.z * Ad[2] + h.w * Ad[3];
    s += __shfl_xor_sync(0xffffffffu, s, 1);
    s += __shfl_xor_sync(0xffffffffu, s, 2);
    d += __shfl_xor_sync(0xffffffffu, d, 1);
    d += __shfl_xor_sync(0xffffffffu, d, 2);
    if (sub == 0) { g_as1[gw * 8 + head] = s; g_ad1[gw * 8 + head] = d; }
}

// ---------------------------------------------------------------------------
// agg1: bucket gather + softmax-normalize + bias + ELU. One warp per dst node.
// ---------------------------------------------------------------------------
__device__ __forceinline__ float edge_w1(int s, int head, float myad) {
    float t = __ldg(g_as1 + s * 8 + head) + myad;
    t = t > 0.f ? t : 0.2f * t;
    return __expf(t);
}

__global__ void __launch_bounds__(256) agg1_kernel(const float* __restrict__ b1) {
    int gw = (blockIdx.x * blockDim.x + threadIdx.x) >> 5;
    int lane = threadIdx.x & 31;
    if (gw >= NN) return;
    int head = lane >> 2;
    int beg = gw * CAP, end = beg + g_deg[gw];
    float myad = g_ad1[gw * 8 + head];
    float a0 = 0.f, a1 = 0.f, a2 = 0.f, a3 = 0.f, den = 0.f;
    int p = beg;
    for (; p + 4 <= end; p += 4) {
        int s0 = g_eidx[p], s1 = g_eidx[p + 1], s2 = g_eidx[p + 2], s3 = g_eidx[p + 3];
        float w0 = edge_w1(s0, head, myad);
        float w1 = edge_w1(s1, head, myad);
        float w2 = edge_w1(s2, head, myad);
        float w3 = edge_w1(s3, head, myad);
        float4 h0 = *(const float4*)(g_hp1 + (size_t)s0 * H1DIM + lane * 4);
        float4 h1 = *(const float4*)(g_hp1 + (size_t)s1 * H1DIM + lane * 4);
        float4 h2 = *(const float4*)(g_hp1 + (size_t)s2 * H1DIM + lane * 4);
        float4 h3 = *(const float4*)(g_hp1 + (size_t)s3 * H1DIM + lane * 4);
        den += (w0 + w1) + (w2 + w3);
        a0 += w0 * h0.x + w1 * h1.x + w2 * h2.x + w3 * h3.x;
        a1 += w0 * h0.y + w1 * h1.y + w2 * h2.y + w3 * h3.y;
        a2 += w0 * h0.z + w1 * h1.z + w2 * h2.z + w3 * h3.z;
        a3 += w0 * h0.w + w1 * h1.w + w2 * h2.w + w3 * h3.w;
    }
    for (; p < end; p++) {
        int s = g_eidx[p];
        float w = edge_w1(s, head, myad);
        float4 h = *(const float4*)(g_hp1 + (size_t)s * H1DIM + lane * 4);
        den += w;
        a0 += w * h.x; a1 += w * h.y; a2 += w * h.z; a3 += w * h.w;
    }
    float inv = __frcp_rn(den);
    const float* bb = b1 + lane * 4;
    float v0 = a0 * inv + bb[0];
    float v1 = a1 * inv + bb[1];
    float v2 = a2 * inv + bb[2];
    float v3 = a3 * inv + bb[3];
    v0 = v0 > 0.f ? v0 : expm1f(v0);
    v1 = v1 > 0.f ? v1 : expm1f(v1);
    v2 = v2 > 0.f ? v2 : expm1f(v2);
    v3 = v3 > 0.f ? v3 : expm1f(v3);
    *(float4*)(g_h1 + (size_t)gw * H1DIM + lane * 4) = make_float4(v0, v1, v2, v3);
}

// ---------------------------------------------------------------------------
// GEMM2 + alpha2 fused
// ---------------------------------------------------------------------------
__global__ void __launch_bounds__(256) gemm2_kernel(const float* __restrict__ W2,
                             const float* __restrict__ as2w, const float* __restrict__ ad2w) {
    __shared__ __align__(16) float Ws[128 * 16];
    __shared__ __align__(16) float Hs[16][132];
    const int tid = threadIdx.x;
    const int row0 = blockIdx.x * 16;
#pragma unroll
    for (int t = 0; t < 2; t++) {
        int i = (tid + t * 256) * 4;
        *(float4*)&Ws[i] = *(const float4*)(W2 + i);
    }
#pragma unroll
    for (int t = 0; t < 2; t++) {
        int i = tid + t * 256;
        int r = i >> 5, c = (i & 31) << 2;
        float4 v = make_float4(0.f, 0.f, 0.f, 0.f);
        int gr = row0 + r;
        if (gr < NN) v = *(const float4*)(g_h1 + (size_t)gr * H1DIM + c);
        *(float4*)&Hs[r][c] = v;
    }
    __syncthreads();
    const int r = tid >> 4, c = tid & 15;
    float s = 0.f;
#pragma unroll
    for (int k = 0; k < 128; k++) s += Hs[r][k] * Ws[k * 16 + c];
    float sv = s * as2w[c], dv = s * ad2w[c];
#pragma unroll
    for (int off = 8; off >= 1; off >>= 1) {
        sv += __shfl_down_sync(0xffffffffu, sv, off, 16);
        dv += __shfl_down_sync(0xffffffffu, dv, off, 16);
    }
    int gr = row0 + r;
    if (gr < NN) {
        g_h2[gr * 16 + c] = s;
        if (c == 0) { g_as2[gr] = sv; g_ad2[gr] = dv; }
    }
}

// ---------------------------------------------------------------------------
// agg2: one warp per dst node; two 16-lane groups; unroll x2.
// Tail: re-zero g_deg for the next replay (kept invariant across launches).
// ---------------------------------------------------------------------------
__global__ void __launch_bounds__(256) agg2_kernel(const float* __restrict__ b2,
                                                   float* __restrict__ out) {
    int gw = (blockIdx.x * blockDim.x + threadIdx.x) >> 5;
    int lane = threadIdx.x & 31;
    if (gw >= NN) return;
    int beg = gw * CAP, end = beg + g_deg[gw];
    int grp = lane >> 4, fl = lane & 15;
    float ad = g_ad2[gw];
    float acc = 0.f, den = 0.f;
    int p = beg + grp;
    for (; p + 2 < end; p += 4) {
        int s0 = g_eidx[p], s1 = g_eidx[p + 2];
        float t0 = g_as2[s0] + ad, t1 = g_as2[s1] + ad;
        t0 = t0 > 0.f ? t0 : 0.2f * t0;
        t1 = t1 > 0.f ? t1 : 0.2f * t1;
        float w0 = __expf(t0), w1 = __expf(t1);
        float v0 = g_h2[s0 * 16 + fl], v1 = g_h2[s1 * 16 + fl];
        den += w0 + w1;
        acc += w0 * v0 + w1 * v1;
    }
    if (p < end) {
        int s = g_eidx[p];
        float t = g_as2[s] + ad;
        t = t > 0.f ? t : 0.2f * t;
        float w = __expf(t);
        den += w;
        acc += w * g_h2[s * 16 + fl];
    }
    acc += __shfl_xor_sync(0xffffffffu, acc, 16);
    den += __shfl_xor_sync(0xffffffffu, den, 16);
    if (grp == 0) out[gw * 16 + fl] = acc * __frcp_rn(den) + b2[fl];
    if (lane == 0) g_deg[gw] = 0;   // reset for next graph replay
}

// ---------------------------------------------------------------------------
extern "C" void kernel_launch(void* const* d_in, const int* in_sizes, int n_in,
                              void* d_out, int out_size) {
    const float* x   = (const float*)d_in[0];
    const int*   ei  = (const int*)d_in[1];
    const float* W1  = (const float*)d_in[2];
    const float* as1 = (const float*)d_in[3];
    const float* ad1 = (const float*)d_in[4];
    const float* b1  = (const float*)d_in[5];
    const float* W2  = (const float*)d_in[6];
    const float* as2 = (const float*)d_in[7];
    const float* ad2 = (const float*)d_in[8];
    const float* b2  = (const float*)d_in[9];
    const int E = in_sizes[1] / 2;
    const int scat_threads = ((E + 3) >> 2) + NN;

    scatter_kernel<<<(scat_threads + 255) / 256, 256>>>(ei, E);
    gemm1_kernel<<<(NN + 127) / 128, 256>>>(x, W1);
    alpha1_kernel<<<(NN * 32 + 255) / 256, 256>>>(as1, ad1);
    agg1_kernel<<<(NN * 32 + 255) / 256, 256>>>(b1);
    gemm2_kernel<<<(NN + 15) / 16, 256>>>(W2, as2, ad2);
    agg2_kernel<<<(NN * 32 + 255) / 256, 256>>>(b2, (float*)d_out);
}

// round 7
// speedup vs baseline: 1.1551x; 1.1287x over previous
#include <cuda_runtime.h>
#include <cuda_fp16.h>

#define NN      50000
#define FDIM    256
#define H1DIM   128
#define NHEADS  8
#define CDIM2   16
#define CAP     96               // max in-degree bucket capacity (Poisson(16) tail: safe)

// ---- scratch (__device__ globals; no allocation allowed) -------------------
__device__ float g_hp1[NN * H1DIM];
__device__ float g_as1[NN * NHEADS];
__device__ float g_ad1[NN * NHEADS];
__device__ float g_h1[NN * H1DIM];
__device__ float g_h2[NN * CDIM2];
__device__ float g_as2[NN];
__device__ float g_ad2[NN];
__device__ int g_deg[NN];              // zero-init; re-zeroed by agg2 tail each launch
__device__ int g_eidx[NN * CAP];       // bucketed incoming-edge src lists

// ---------------------------------------------------------------------------
// scatter: single-pass bucket build. 4 real edges per thread + self-loop range.
// ---------------------------------------------------------------------------
__global__ void scatter_kernel(const int* __restrict__ ei, int E) {
    int quads = (E + 3) >> 2;
    int idx = blockIdx.x * blockDim.x + threadIdx.x;
    if (idx < quads) {
        int e0 = idx * 4;
        int n = min(4, E - e0);
        int s0, s1, s2, s3, d0, d1, d2, d3;
        s0 = ei[e0];     d0 = ei[E + e0];
        if (n > 1) { s1 = ei[e0 + 1]; d1 = ei[E + e0 + 1]; }
        if (n > 2) { s2 = ei[e0 + 2]; d2 = ei[E + e0 + 2]; }
        if (n > 3) { s3 = ei[e0 + 3]; d3 = ei[E + e0 + 3]; }
        int p0 = atomicAdd(&g_deg[d0], 1);
        int p1 = (n > 1) ? atomicAdd(&g_deg[d1], 1) : 0;
        int p2 = (n > 2) ? atomicAdd(&g_deg[d2], 1) : 0;
        int p3 = (n > 3) ? atomicAdd(&g_deg[d3], 1) : 0;
        g_eidx[d0 * CAP + p0] = s0;
        if (n > 1) g_eidx[d1 * CAP + p1] = s1;
        if (n > 2) g_eidx[d2 * CAP + p2] = s2;
        if (n > 3) g_eidx[d3 * CAP + p3] = s3;
    } else if (idx < quads + NN) {
        int nd = idx - quads;
        int p = atomicAdd(&g_deg[nd], 1);
        g_eidx[nd * CAP + p] = nd;     // self-loop
    }
}

// ---------------------------------------------------------------------------
// GEMM1 (fp16 MMA, fp32 accum + fused alpha epilogue):
//   g_hp1[N,128] = x[N,256] @ W1[256,128]   (fp32 output)
//   g_as1/g_ad1  = per-node attention logits (from fp16-staged tile)
// 128x128 tile, 8 warps in 4(m)x2(n); each warp 32x64 via m16n8k16.
// ---------------------------------------------------------------------------
__global__ void __launch_bounds__(256) gemm1_kernel(const float* __restrict__ X,
                                                    const float* __restrict__ W,
                                                    const float* __restrict__ att_src,
                                                    const float* __restrict__ att_dst) {
    union SmemU {
        struct { __half A[128][40]; __half B[128][40]; } ld;   // MMA tiles
        __half stage[128][136];                                 // epilogue staging
    };
    __shared__ __align__(16) SmemU su;
    const int tid = threadIdx.x;
    const int warp = tid >> 5, lane = tid & 31;
    const int wm = warp >> 1, wn = warp & 1;
    const int row0 = blockIdx.x * 128;
    const int gid = lane >> 2, qid = lane & 3;

    float acc[2][8][4];
#pragma unroll
    for (int mt = 0; mt < 2; mt++)
#pragma unroll
        for (int nt = 0; nt < 8; nt++)
#pragma unroll
            for (int j = 0; j < 4; j++) acc[mt][nt][j] = 0.f;

    for (int k0 = 0; k0 < FDIM; k0 += 32) {
        // A tile: 128x32 -> fp16
#pragma unroll
        for (int t = 0; t < 4; t++) {
            int i = tid + t * 256;
            int r = i >> 3, c = (i & 7) << 2;
            float4 v = make_float4(0.f, 0.f, 0.f, 0.f);
            if (row0 + r < NN) v = *(const float4*)(X + (size_t)(row0 + r) * FDIM + k0 + c);
            *(__half2*)&su.ld.A[r][c]     = __floats2half2_rn(v.x, v.y);
            *(__half2*)&su.ld.A[r][c + 2] = __floats2half2_rn(v.z, v.w);
        }
        // B tile: 32(k)x128(n), stored transposed [n][k] as fp16
#pragma unroll
        for (int t = 0; t < 4; t++) {
            int i = tid + t * 256;
            int r = i & 31;             // k within chunk
            int c = (i >> 5) << 2;      // n
            float4 v = *(const float4*)(W + (size_t)(k0 + r) * H1DIM + c);
            su.ld.B[c + 0][r] = __float2half_rn(v.x);
            su.ld.B[c + 1][r] = __float2half_rn(v.y);
            su.ld.B[c + 2][r] = __float2half_rn(v.z);
            su.ld.B[c + 3][r] = __float2half_rn(v.w);
        }
        __syncthreads();
#pragma unroll
        for (int kk = 0; kk < 2; kk++) {
            const int ks = kk * 16;
            unsigned a[2][4], b[8][2];
#pragma unroll
            for (int mt = 0; mt < 2; mt++) {
                int rw = wm * 32 + mt * 16 + gid;
                a[mt][0] = *(const unsigned*)&su.ld.A[rw][ks + qid * 2];
                a[mt][1] = *(const unsigned*)&su.ld.A[rw + 8][ks + qid * 2];
                a[mt][2] = *(const unsigned*)&su.ld.A[rw][ks + 8 + qid * 2];
                a[mt][3] = *(const unsigned*)&su.ld.A[rw + 8][ks + 8 + qid * 2];
            }
#pragma unroll
            for (int nt = 0; nt < 8; nt++) {
                int cl = wn * 64 + nt * 8 + gid;
                b[nt][0] = *(const unsigned*)&su.ld.B[cl][ks + qid * 2];
                b[nt][1] = *(const unsigned*)&su.ld.B[cl][ks + 8 + qid * 2];
            }
#pragma unroll
            for (int mt = 0; mt < 2; mt++)
#pragma unroll
                for (int nt = 0; nt < 8; nt++) {
                    asm volatile(
                        "mma.sync.aligned.m16n8k16.row.col.f32.f16.f16.f32 "
                        "{%0,%1,%2,%3}, {%4,%5,%6,%7}, {%8,%9}, {%0,%1,%2,%3};\n"
                        : "+f"(acc[mt][nt][0]), "+f"(acc[mt][nt][1]),
                          "+f"(acc[mt][nt][2]), "+f"(acc[mt][nt][3])
                        : "r"(a[mt][0]), "r"(a[mt][1]), "r"(a[mt][2]), "r"(a[mt][3]),
                          "r"(b[nt][0]), "r"(b[nt][1]));
                }
        }
        __syncthreads();
    }
    // epilogue: store fp32 h to gmem + fp16 tile to smem stage
#pragma unroll
    for (int mt = 0; mt < 2; mt++) {
        int r0 = wm * 32 + mt * 16 + gid;
        int grw = row0 + r0;
#pragma unroll
        for (int nt = 0; nt < 8; nt++) {
            int cl = wn * 64 + nt * 8 + qid * 2;
            *(__half2*)&su.stage[r0][cl]     = __floats2half2_rn(acc[mt][nt][0], acc[mt][nt][1]);
            *(__half2*)&su.stage[r0 + 8][cl] = __floats2half2_rn(acc[mt][nt][2], acc[mt][nt][3]);
            if (grw < NN)
                *(float2*)(g_hp1 + (size_t)grw * H1DIM + cl) =
                    make_float2(acc[mt][nt][0], acc[mt][nt][1]);
            if (grw + 8 < NN)
                *(float2*)(g_hp1 + (size_t)(grw + 8) * H1DIM + cl) =
                    make_float2(acc[mt][nt][2], acc[mt][nt][3]);
        }
    }
    __syncthreads();
    // alpha epilogue: each warp computes logits for 16 rows of the tile
    {
        int head = lane >> 2, sub = lane & 3;
        float4 A4 = *(const float4*)(att_src + head * 16 + sub * 4);
        float4 D4 = *(const float4*)(att_dst + head * 16 + sub * 4);
#pragma unroll
        for (int rr = 0; rr < 16; rr++) {
            int r = warp * 16 + rr;
            int grow = row0 + r;
            if (grow >= NN) break;
            float2 f01 = __half22float2(*(__half2*)&su.stage[r][lane * 4]);
            float2 f23 = __half22float2(*(__half2*)&su.stage[r][lane * 4 + 2]);
            float s = f01.x * A4.x + f01.y * A4.y + f23.x * A4.z + f23.y * A4.w;
            float d = f01.x * D4.x + f01.y * D4.y + f23.x * D4.z + f23.y * D4.w;
            s += __shfl_xor_sync(0xffffffffu, s, 1);
            s += __shfl_xor_sync(0xffffffffu, s, 2);
            d += __shfl_xor_sync(0xffffffffu, d, 1);
            d += __shfl_xor_sync(0xffffffffu, d, 2);
            if (sub == 0) { g_as1[grow * 8 + head] = s; g_ad1[grow * 8 + head] = d; }
        }
    }
}

// ---------------------------------------------------------------------------
// agg1: bucket gather + softmax-normalize + bias + ELU. One warp per dst node.
// ---------------------------------------------------------------------------
__device__ __forceinline__ float edge_w1(int s, int head, float myad) {
    float t = __ldg(g_as1 + s * 8 + head) + myad;
    t = t > 0.f ? t : 0.2f * t;
    return __expf(t);
}

__global__ void __launch_bounds__(256) agg1_kernel(const float* __restrict__ b1) {
    int gw = (blockIdx.x * blockDim.x + threadIdx.x) >> 5;
    int lane = threadIdx.x & 31;
    if (gw >= NN) return;
    int head = lane >> 2;
    int beg = gw * CAP, end = beg + g_deg[gw];
    float myad = g_ad1[gw * 8 + head];
    float a0 = 0.f, a1 = 0.f, a2 = 0.f, a3 = 0.f, den = 0.f;
    int p = beg;
    for (; p + 4 <= end; p += 4) {
        int s0 = g_eidx[p], s1 = g_eidx[p + 1], s2 = g_eidx[p + 2], s3 = g_eidx[p + 3];
        float w0 = edge_w1(s0, head, myad);
        float w1 = edge_w1(s1, head, myad);
        float w2 = edge_w1(s2, head, myad);
        float w3 = edge_w1(s3, head, myad);
        float4 h0 = *(const float4*)(g_hp1 + (size_t)s0 * H1DIM + lane * 4);
        float4 h1 = *(const float4*)(g_hp1 + (size_t)s1 * H1DIM + lane * 4);
        float4 h2 = *(const float4*)(g_hp1 + (size_t)s2 * H1DIM + lane * 4);
        float4 h3 = *(const float4*)(g_hp1 + (size_t)s3 * H1DIM + lane * 4);
        den += (w0 + w1) + (w2 + w3);
        a0 += w0 * h0.x + w1 * h1.x + w2 * h2.x + w3 * h3.x;
        a1 += w0 * h0.y + w1 * h1.y + w2 * h2.y + w3 * h3.y;
        a2 += w0 * h0.z + w1 * h1.z + w2 * h2.z + w3 * h3.z;
        a3 += w0 * h0.w + w1 * h1.w + w2 * h2.w + w3 * h3.w;
    }
    for (; p < end; p++) {
        int s = g_eidx[p];
        float w = edge_w1(s, head, myad);
        float4 h = *(const float4*)(g_hp1 + (size_t)s * H1DIM + lane * 4);
        den += w;
        a0 += w * h.x; a1 += w * h.y; a2 += w * h.z; a3 += w * h.w;
    }
    float inv = __frcp_rn(den);
    const float* bb = b1 + lane * 4;
    float v0 = a0 * inv + bb[0];
    float v1 = a1 * inv + bb[1];
    float v2 = a2 * inv + bb[2];
    float v3 = a3 * inv + bb[3];
    v0 = v0 > 0.f ? v0 : __expf(v0) - 1.f;
    v1 = v1 > 0.f ? v1 : __expf(v1) - 1.f;
    v2 = v2 > 0.f ? v2 : __expf(v2) - 1.f;
    v3 = v3 > 0.f ? v3 : __expf(v3) - 1.f;
    *(float4*)(g_h1 + (size_t)gw * H1DIM + lane * 4) = make_float4(v0, v1, v2, v3);
}

// ---------------------------------------------------------------------------
// GEMM2 + alpha2 fused
// ---------------------------------------------------------------------------
__global__ void __launch_bounds__(256) gemm2_kernel(const float* __restrict__ W2,
                             const float* __restrict__ as2w, const float* __restrict__ ad2w) {
    __shared__ __align__(16) float Ws[128 * 16];
    __shared__ __align__(16) float Hs[16][132];
    const int tid = threadIdx.x;
    const int row0 = blockIdx.x * 16;
#pragma unroll
    for (int t = 0; t < 2; t++) {
        int i = (tid + t * 256) * 4;
        *(float4*)&Ws[i] = *(const float4*)(W2 + i);
    }
#pragma unroll
    for (int t = 0; t < 2; t++) {
        int i = tid + t * 256;
        int r = i >> 5, c = (i & 31) << 2;
        float4 v = make_float4(0.f, 0.f, 0.f, 0.f);
        int gr = row0 + r;
        if (gr < NN) v = *(const float4*)(g_h1 + (size_t)gr * H1DIM + c);
        *(float4*)&Hs[r][c] = v;
    }
    __syncthreads();
    const int r = tid >> 4, c = tid & 15;
    float s = 0.f;
#pragma unroll
    for (int k = 0; k < 128; k++) s += Hs[r][k] * Ws[k * 16 + c];
    float sv = s * as2w[c], dv = s * ad2w[c];
#pragma unroll
    for (int off = 8; off >= 1; off >>= 1) {
        sv += __shfl_down_sync(0xffffffffu, sv, off, 16);
        dv += __shfl_down_sync(0xffffffffu, dv, off, 16);
    }
    int gr = row0 + r;
    if (gr < NN) {
        g_h2[gr * 16 + c] = s;
        if (c == 0) { g_as2[gr] = sv; g_ad2[gr] = dv; }
    }
}

// ---------------------------------------------------------------------------
// agg2: one warp per dst node; two 16-lane groups; unroll x2.
// Tail: re-zero g_deg for the next replay (kept invariant across launches).
// ---------------------------------------------------------------------------
__global__ void __launch_bounds__(256) agg2_kernel(const float* __restrict__ b2,
                                                   float* __restrict__ out) {
    int gw = (blockIdx.x * blockDim.x + threadIdx.x) >> 5;
    int lane = threadIdx.x & 31;
    if (gw >= NN) return;
    int beg = gw * CAP, end = beg + g_deg[gw];
    int grp = lane >> 4, fl = lane & 15;
    float ad = g_ad2[gw];
    float acc = 0.f, den = 0.f;
    int p = beg + grp;
    for (; p + 2 < end; p += 4) {
        int s0 = g_eidx[p], s1 = g_eidx[p + 2];
        float t0 = g_as2[s0] + ad, t1 = g_as2[s1] + ad;
        t0 = t0 > 0.f ? t0 : 0.2f * t0;
        t1 = t1 > 0.f ? t1 : 0.2f * t1;
        float w0 = __expf(t0), w1 = __expf(t1);
        float v0 = g_h2[s0 * 16 + fl], v1 = g_h2[s1 * 16 + fl];
        den += w0 + w1;
        acc += w0 * v0 + w1 * v1;
    }
    if (p < end) {
        int s = g_eidx[p];
        float t = g_as2[s] + ad;
        t = t > 0.f ? t : 0.2f * t;
        float w = __expf(t);
        den += w;
        acc += w * g_h2[s * 16 + fl];
    }
    acc += __shfl_xor_sync(0xffffffffu, acc, 16);
    den += __shfl_xor_sync(0xffffffffu, den, 16);
    if (grp == 0) out[gw * 16 + fl] = acc * __frcp_rn(den) + b2[fl];
    if (lane == 0) g_deg[gw] = 0;   // reset for next graph replay
}

// ---------------------------------------------------------------------------
extern "C" void kernel_launch(void* const* d_in, const int* in_sizes, int n_in,
                              void* d_out, int out_size) {
    const float* x   = (const float*)d_in[0];
    const int*   ei  = (const int*)d_in[1];
    const float* W1  = (const float*)d_in[2];
    const float* as1 = (const float*)d_in[3];
    const float* ad1 = (const float*)d_in[4];
    const float* b1  = (const float*)d_in[5];
    const float* W2  = (const float*)d_in[6];
    const float* as2 = (const float*)d_in[7];
    const float* ad2 = (const float*)d_in[8];
    const float* b2  = (const float*)d_in[9];
    const int E = in_sizes[1] / 2;
    const int scat_threads = ((E + 3) >> 2) + NN;

    scatter_kernel<<<(scat_threads + 255) / 256, 256>>>(ei, E);
    gemm1_kernel<<<(NN + 127) / 128, 256>>>(x, W1, as1, ad1);
    agg1_kernel<<<(NN * 32 + 255) / 256, 256>>>(b1);
    gemm2_kernel<<<(NN + 15) / 16, 256>>>(W2, as2, ad2);
    agg2_kernel<<<(NN * 32 + 255) / 256, 256>>>(b2, (float*)d_out);
}